// round 3
// baseline (speedup 1.0000x reference)
#include <cuda_runtime.h>
#include <math.h>

#define NJ 33
#define FD 256
#define MAXB 4096
#define NNMAX (MAXB*NJ)
#define MAXE 165

// ---- scratch (no allocations allowed) ----
__device__ float g_bufA[(size_t)NNMAX*FD];
__device__ float g_bufB[(size_t)NNMAX*FD];
__device__ float g_sum[FD], g_sumsq[FD];
__device__ float g_scale[FD], g_shift[FD];
__device__ int   g_rp[NJ+1];
__device__ int   g_ci[MAXE];
__device__ float g_av[MAXE];
__device__ float g_acol[NJ];
__device__ float g_whc[FD*4];
__device__ float g_bhc[4];

// ============================================================
// Prep: normalized adjacency CSR (graph 0 = template for all),
// pooled column weights a_col, fused classifier whc = wh@wc.
// ============================================================
__global__ void prep_kernel(const int* __restrict__ src, const int* __restrict__ dst,
                            int epg,
                            const float* __restrict__ wh, const float* __restrict__ wc,
                            const float* __restrict__ bh, const float* __restrict__ bc) {
    __shared__ float s_dinv[NJ];
    int tid = threadIdx.x;
    if (tid < NJ) {
        int d = 0;
        for (int e = 0; e < epg; ++e) d += (dst[e] == tid);
        s_dinv[tid] = rsqrtf((float)d);
    }
    if (tid < FD) { g_sum[tid] = 0.f; g_sumsq[tid] = 0.f; }
    __syncthreads();
    if (tid == 0) {
        int pos = 0;
        for (int j = 0; j < NJ; ++j) {
            g_rp[j] = pos;
            for (int e = 0; e < epg && pos < MAXE; ++e) {
                if (dst[e] == j) {
                    int r = src[e];
                    g_ci[pos] = r;
                    g_av[pos] = s_dinv[r] * s_dinv[j];
                    pos++;
                }
            }
        }
        g_rp[NJ] = pos;
    }
    if (tid < NJ) {
        float s = 0.f;
        for (int e = 0; e < epg; ++e)
            if (src[e] == tid) s += s_dinv[tid] * s_dinv[dst[e]];
        g_acol[tid] = s / (float)NJ;
    }
    for (int idx = tid; idx < FD*4; idx += blockDim.x) {
        int k = idx >> 2, l = idx & 3;
        float s = 0.f;
        for (int c = 0; c < FD; ++c) s += wh[k*FD + c] * wc[c*4 + l];
        g_whc[idx] = s;
    }
    if (tid < 4) {
        float s = 0.f;
        for (int c = 0; c < FD; ++c) s += bh[c] * wc[c*4 + tid];
        g_bhc[tid] = s + bc[tid];
    }
}

// ============================================================
// Fused GCN layer: (pre BN+ReLU) -> h@W -> A_hat@y + b
// One block per graph. 256 threads = 128 column-pairs x 2 row-halves.
//   cp   = tid & 127 : owns output columns {2cp, 2cp+1}
//   half = tid >> 7  : GEMM rows R0..R0+16 (R0 = 0 or 16);
//                      owns rows R0+rrStart..R0+16 (rrStart = half)
// ============================================================
__global__ void __launch_bounds__(256)
layer_kernel(const float* __restrict__ in_ext,
             const float* __restrict__ W,
             const float* __restrict__ bias,
             int mode /*0 = nan_to_num, 1 = BN+relu*/,
             int in_sel, int out_sel) {
    __shared__ float sh[NJ*FD];          // input tile, then reused for y
    __shared__ int   s_rp[NJ+1];
    __shared__ int   s_ci[MAXE];
    __shared__ float s_av[MAXE];

    const int tid  = threadIdx.x;
    const int cp   = tid & 127;
    const int half = tid >> 7;
    const int R0   = half ? 16 : 0;
    const int rrS  = half;               // first owned rr
    const int b    = blockIdx.x;

    const float* in = (in_sel == 1) ? g_bufA : (in_sel == 2) ? g_bufB : in_ext;
    float*      out = (out_sel == 1) ? g_bufA : g_bufB;
    const float* inb = in + (size_t)b * NJ * FD;

    float sc = 1.f, shf = 0.f;
    if (mode == 1) { sc = g_scale[tid]; shf = g_shift[tid]; }

    // Load input tile; channel == tid for every row (coalesced).
    #pragma unroll
    for (int r = 0; r < NJ; ++r) {
        float v = inb[r*FD + tid];
        if (mode == 0) { if (v != v) v = 0.f; }
        else           { v = fmaxf(fmaf(v, sc, shf), 0.f); }
        sh[r*FD + tid] = v;
    }
    if (tid <= NJ) s_rp[tid] = g_rp[tid];
    if (tid < MAXE) { s_ci[tid] = g_ci[tid]; s_av[tid] = g_av[tid]; }
    __syncthreads();

    // GEMM: y[r][2cp..2cp+1] for r = R0..R0+16
    float2 acc[17];
    #pragma unroll
    for (int rr = 0; rr < 17; ++rr) acc[rr] = make_float2(0.f, 0.f);

    const float2* __restrict__ W2  = (const float2*)W;
    const float2* __restrict__ sh2 = (const float2*)sh;
    #pragma unroll 4
    for (int k = 0; k < FD; k += 2) {
        const float2 wa = W2[ k      * (FD/2) + cp];
        const float2 wb = W2[(k + 1) * (FD/2) + cp];
        const int k2 = k >> 1;
        #pragma unroll
        for (int rr = 0; rr < 17; ++rr) {
            const float2 h2 = sh2[(R0 + rr)*(FD/2) + k2];   // broadcast LDS.64
            acc[rr].x = fmaf(h2.x, wa.x, acc[rr].x);
            acc[rr].x = fmaf(h2.y, wb.x, acc[rr].x);
            acc[rr].y = fmaf(h2.x, wa.y, acc[rr].y);
            acc[rr].y = fmaf(h2.y, wb.y, acc[rr].y);
        }
    }

    // Stage y into smem (overwrites input tile) for sparse row gather.
    __syncthreads();
    #pragma unroll
    for (int rr = 1; rr < 17; ++rr)
        ((float2*)sh)[(R0 + rr)*(FD/2) + cp] = acc[rr];
    if (rrS == 0)
        ((float2*)sh)[R0*(FD/2) + cp] = acc[0];
    __syncthreads();

    // Sparse epilogue over owned rows; BN sum accumulation.
    const float2 bia = ((const float2*)bias)[cp];
    float2 s1 = make_float2(0.f, 0.f), s2 = make_float2(0.f, 0.f);
    float* outb = out + (size_t)b * NJ * FD;

    for (int rr = rrS; rr < 17; ++rr) {
        const int j = R0 + rr;
        float zx = bia.x, zy = bia.y;
        const int p0 = s_rp[j], p1 = s_rp[j+1];
        for (int p = p0; p < p1; ++p) {
            const int   r = s_ci[p];
            const float a = s_av[p];
            const float2 y = ((float2*)sh)[r*(FD/2) + cp];
            zx = fmaf(a, y.x, zx);
            zy = fmaf(a, y.y, zy);
        }
        ((float2*)outb)[j*(FD/2) + cp] = make_float2(zx, zy);
        s1.x += zx; s1.y += zy;
        s2.x = fmaf(zx, zx, s2.x); s2.y = fmaf(zy, zy, s2.y);
    }
    atomicAdd(&g_sum[2*cp],       s1.x);
    atomicAdd(&g_sum[2*cp + 1],   s1.y);
    atomicAdd(&g_sumsq[2*cp],     s2.x);
    atomicAdd(&g_sumsq[2*cp + 1], s2.y);
}

// ============================================================
__global__ void stats_kernel(const float* __restrict__ g, const float* __restrict__ be,
                             float inv_nn) {
    int tid = threadIdx.x;
    float mu  = g_sum[tid] * inv_nn;
    float var = g_sumsq[tid] * inv_nn - mu * mu;
    float rs  = rsqrtf(var + 1e-5f);
    float sc  = rs * g[tid];
    g_scale[tid] = sc;
    g_shift[tid] = be[tid] - mu * sc;
    g_sum[tid] = 0.f; g_sumsq[tid] = 0.f;
}

// ============================================================
// Final fused layer: BN2+ReLU -> a_col^T h -> @ (wh@wc) + bhc
// ============================================================
__global__ void __launch_bounds__(256)
final_kernel(float* __restrict__ out) {
    __shared__ float s_acol[NJ];
    __shared__ float s_red[8][4];
    const int tid = threadIdx.x;
    const int b   = blockIdx.x;
    if (tid < NJ) s_acol[tid] = g_acol[tid];
    __syncthreads();

    const float sc  = g_scale[tid];
    const float shf = g_shift[tid];
    const float* inb = g_bufA + (size_t)b * NJ * FD;

    float v = 0.f;
    #pragma unroll
    for (int r = 0; r < NJ; ++r) {
        float x = inb[r*FD + tid];
        x = fmaxf(fmaf(x, sc, shf), 0.f);
        v = fmaf(s_acol[r], x, v);
    }
    float4 w = ((const float4*)g_whc)[tid];
    float p0 = v * w.x, p1 = v * w.y, p2 = v * w.z, p3 = v * w.w;
    #pragma unroll
    for (int o = 16; o; o >>= 1) {
        p0 += __shfl_down_sync(0xffffffffu, p0, o);
        p1 += __shfl_down_sync(0xffffffffu, p1, o);
        p2 += __shfl_down_sync(0xffffffffu, p2, o);
        p3 += __shfl_down_sync(0xffffffffu, p3, o);
    }
    const int lane = tid & 31, wid = tid >> 5;
    if (lane == 0) { s_red[wid][0] = p0; s_red[wid][1] = p1; s_red[wid][2] = p2; s_red[wid][3] = p3; }
    __syncthreads();
    if (tid < 4) {
        float s = 0.f;
        #pragma unroll
        for (int w8 = 0; w8 < 8; ++w8) s += s_red[w8][tid];
        out[b*4 + tid] = s + g_bhc[tid];
    }
}

// ============================================================
extern "C" void kernel_launch(void* const* d_in, const int* in_sizes, int n_in,
                              void* d_out, int out_size) {
    const float* x   = (const float*)d_in[0];
    const float* w0  = (const float*)d_in[1];
    const float* b0  = (const float*)d_in[2];
    const float* gg0 = (const float*)d_in[3];
    const float* be0 = (const float*)d_in[4];
    const float* w1  = (const float*)d_in[5];
    const float* b1  = (const float*)d_in[6];
    const float* gg1 = (const float*)d_in[7];
    const float* be1 = (const float*)d_in[8];
    const float* w2  = (const float*)d_in[9];
    const float* b2  = (const float*)d_in[10];
    const float* gg2 = (const float*)d_in[11];
    const float* be2 = (const float*)d_in[12];
    const float* wh  = (const float*)d_in[13];
    const float* bh  = (const float*)d_in[14];
    const float* wc  = (const float*)d_in[15];
    const float* bc  = (const float*)d_in[16];
    const int*   src = (const int*)d_in[17];
    const int*   dst = (const int*)d_in[18];
    float* out = (float*)d_out;

    const int B   = in_sizes[0] / (NJ * FD);
    const int epg = in_sizes[17] / B;
    const float inv_nn = 1.0f / (float)(B * NJ);

    prep_kernel<<<1, 256>>>(src, dst, epg, wh, wc, bh, bc);

    layer_kernel<<<B, 256>>>(x, w0, b0, /*mode=*/0, /*in_sel=*/0, /*out_sel=*/1);
    stats_kernel<<<1, 256>>>(gg0, be0, inv_nn);
    layer_kernel<<<B, 256>>>(nullptr, w1, b1, 1, 1, 2);
    stats_kernel<<<1, 256>>>(gg1, be1, inv_nn);
    layer_kernel<<<B, 256>>>(nullptr, w2, b2, 1, 2, 1);
    stats_kernel<<<1, 256>>>(gg2, be2, inv_nn);
    final_kernel<<<B, 256>>>(out);
}